// round 3
// baseline (speedup 1.0000x reference)
#include <cuda_runtime.h>
#include <math.h>

// ---------------- problem constants ----------------
#define T_TOK   1024
#define HDIM    1024
#define NEXP    64
#define IDIM    512
#define TOPK    6
#define NGRP    8
#define TKGRP   3
#define CAP     256
#define SCALE_F 2.5f

// ---------------- device scratch (no runtime allocs allowed) ----------------
__device__ float g_act[NEXP * CAP * IDIM];       // 32 MB  routed act (silu*up)
__device__ float g_y[NEXP * CAP * HDIM];         // 64 MB  routed down output per slot
__device__ float g_shact[T_TOK * HDIM];          //  4 MB  shared-expert act
__device__ float g_shared[T_TOK * HDIM];         //  4 MB  shared-expert output
__device__ int   g_cnt[NEXP];
__device__ int   g_slot_tok[NEXP * CAP];         // token index per (expert, slot)
__device__ int   g_slot_of_a[T_TOK * TOPK];      // slot (e*CAP+pos) per assignment, -1 dropped
__device__ float g_topk_w[T_TOK * TOPK];         // normalized routing weights

// ---------------- f32x2 helpers (Blackwell packed fp32 FMA) ----------------
__device__ __forceinline__ unsigned long long pk2(float lo, float hi) {
    unsigned long long r;
    asm("mov.b64 %0, {%1, %2};" : "=l"(r) : "f"(lo), "f"(hi));
    return r;
}
__device__ __forceinline__ void ffma2(unsigned long long& d, unsigned long long a, unsigned long long b) {
    asm("fma.rn.f32x2 %0, %1, %2, %0;" : "+l"(d) : "l"(a), "l"(b));
}
__device__ __forceinline__ float2 upk2(unsigned long long v) {
    float lo, hi;
    asm("mov.b64 {%0, %1}, %2;" : "=f"(lo), "=f"(hi) : "l"(v));
    return make_float2(lo, hi);
}

// ---------------- zero expert counters ----------------
__global__ void zero_cnt_kernel() {
    int i = threadIdx.x;
    if (i < NEXP) g_cnt[i] = 0;
}

// ---------------- router: logits GEMM + grouped noaux_tc top-k + dispatch ----------------
__global__ void router_kernel(const float* __restrict__ x,
                              const float* __restrict__ gate_w,
                              const float* __restrict__ e_bias) {
    __shared__ float xs[HDIM];
    __shared__ float part[256];
    __shared__ float logits[NEXP];
    const int t = blockIdx.x, tid = threadIdx.x;

    ((float4*)xs)[tid] = ((const float4*)(x + (long long)t * HDIM))[tid];
    __syncthreads();

    const int e = tid & 63, p = tid >> 6;
    float acc = 0.f;
    const int h0 = p * 256;
#pragma unroll 8
    for (int h = h0; h < h0 + 256; ++h)
        acc = fmaf(xs[h], gate_w[h * NEXP + e], acc);
    part[tid] = acc;
    __syncthreads();
    if (tid < 64)
        logits[tid] = part[tid] + part[tid + 64] + part[tid + 128] + part[tid + 192];
    __syncthreads();

    if (tid == 0) {
        float sc[NEXP], s[NEXP];
        for (int i = 0; i < NEXP; ++i) {
            float v = 1.f / (1.f + expf(-logits[i]));   // sigmoid scores
            sc[i] = v;
            s[i]  = v + e_bias[i];                      // bias-corrected selection score
        }
        // group score = sum of top-2 within each group of 8
        float gs[NGRP];
        for (int gi = 0; gi < NGRP; ++gi) {
            float m1 = -1e30f, m2 = -1e30f;
            for (int j = 0; j < 8; ++j) {
                float v = s[gi * 8 + j];
                if (v > m1) { m2 = m1; m1 = v; }
                else if (v > m2) m2 = v;
            }
            gs[gi] = m1 + m2;
        }
        // top-TKGRP groups (strict >, ascending scan -> lowest index on ties, jax-stable)
        bool gpick[NGRP];
        for (int gi = 0; gi < NGRP; ++gi) gpick[gi] = false;
        for (int r = 0; r < TKGRP; ++r) {
            float best = -1e30f; int bi = 0;
            for (int gi = 0; gi < NGRP; ++gi)
                if (!gpick[gi] && gs[gi] > best) { best = gs[gi]; bi = gi; }
            gpick[bi] = true;
        }
        // top-TOPK experts among masked groups
        bool epick[NEXP];
        for (int i = 0; i < NEXP; ++i) epick[i] = false;
        int   eidx[TOPK];
        float wv[TOPK];
        float wsum = 0.f;
        for (int r = 0; r < TOPK; ++r) {
            float best = -1e30f; int bi = 0;
            for (int i = 0; i < NEXP; ++i)
                if (gpick[i >> 3] && !epick[i] && s[i] > best) { best = s[i]; bi = i; }
            epick[bi] = true;
            eidx[r] = bi;
            wv[r]  = sc[bi];       // weights from un-biased scores
            wsum  += sc[bi];
        }
        const float inv = 1.f / wsum;
        for (int r = 0; r < TOPK; ++r) {
            g_topk_w[t * TOPK + r] = wv[r] * inv;
            const int ex = eidx[r];
            const int pos = atomicAdd(&g_cnt[ex], 1);
            if (pos < CAP) {
                g_slot_tok[ex * CAP + pos]  = t;
                g_slot_of_a[t * TOPK + r]   = ex * CAP + pos;
            } else {
                g_slot_of_a[t * TOPK + r]   = -1;   // capacity drop
            }
        }
    }
}

// ---------------- templated grouped SGEMM (f32x2 micro-kernel) ----------------
// Block computes BM=64 rows x two BN=64 column tiles (G-tile + U-tile).
//   SILU=true : U-tile is B columns at +pair_off; epilogue writes silu(g)*u (one tile).
//   SILU=false: U-tile is B columns at +64 of a 128-wide output tile; plain writes.
// MODE: 0 direct rows, 1 gather token rows via slot_tok, 2 expert-offset rows.
#define BM 64
#define BN 64
#define BK 16

enum { MODE_DIRECT = 0, MODE_GATHER = 1, MODE_EXPOFF = 2 };

template <int MODE, bool SILU>
__global__ __launch_bounds__(256, 2)
void sgemm_moe(const float* __restrict__ A, const float* __restrict__ B,
               float* __restrict__ Cmat,
               int Kdim, int ldA, int ldB, int ldC,
               int pair_off,
               long long strideAe, long long strideBe, long long strideCe,
               int Mfixed) {
    const int e = blockIdx.z;
    int M;
    if (MODE == MODE_DIRECT) {
        M = Mfixed;
    } else {
        int c = g_cnt[e];
        M = (c < CAP) ? c : CAP;
    }
    const int row0 = blockIdx.y * BM;
    if (row0 >= M) return;
    const int col0 = blockIdx.x * (SILU ? BN : 2 * BN);

    const float* Ae = A + (long long)e * strideAe;
    const float* Be = B + (long long)e * strideBe;
    float*       Ce = Cmat + (long long)e * strideCe;

    __shared__ __align__(16) float As[2][BK][BM];
    __shared__ __align__(16) float Bgs[2][BK][BN];
    __shared__ __align__(16) float Bus[2][BK][BN];
    __shared__ int s_toks[BM];

    const int tid = threadIdx.x;
    const int tx = tid & 15, ty = tid >> 4;   // compute layout 16x16
    const int lr = tid >> 2, lc = tid & 3;    // A loader: row, float4-col
    const int lbk = tid >> 4, lbn = tid & 15; // B loader: k-row, float4-col

    if (MODE == MODE_GATHER) {
        if (tid < BM) {
            int r = row0 + tid;
            if (r >= M) r = M - 1;
            s_toks[tid] = g_slot_tok[e * CAP + r];
        }
    }
    __syncthreads();

    const float* aptr;
    if (MODE == MODE_GATHER) {
        aptr = Ae + (long long)s_toks[lr] * ldA + lc * 4;
    } else {
        int r = row0 + lr;
        if (MODE == MODE_EXPOFF && r >= M) r = M - 1;
        aptr = Ae + (long long)r * ldA + lc * 4;
    }
    const float* bptr  = Be + (long long)lbk * ldB + col0 + lbn * 4;
    const float* buptr = bptr + pair_off;

    unsigned long long accg[4][2] = {{0ull,0ull},{0ull,0ull},{0ull,0ull},{0ull,0ull}};
    unsigned long long accu[4][2] = {{0ull,0ull},{0ull,0ull},{0ull,0ull},{0ull,0ull}};

    // prologue: stage 0
    float4 ra  = *(const float4*)aptr;
    float4 rbg = *(const float4*)bptr;
    float4 rbu = *(const float4*)buptr;
    As[0][lc * 4 + 0][lr] = ra.x;
    As[0][lc * 4 + 1][lr] = ra.y;
    As[0][lc * 4 + 2][lr] = ra.z;
    As[0][lc * 4 + 3][lr] = ra.w;
    *(float4*)&Bgs[0][lbk][lbn * 4] = rbg;
    *(float4*)&Bus[0][lbk][lbn * 4] = rbu;
    __syncthreads();

    const int KT = Kdim >> 4;
    for (int kt = 0; kt < KT; ++kt) {
        const int cur = kt & 1;
        const bool more = (kt + 1 < KT);
        if (more) {
            ra  = *(const float4*)(aptr + (kt + 1) * BK);
            rbg = *(const float4*)(bptr  + (long long)(kt + 1) * BK * ldB);
            rbu = *(const float4*)(buptr + (long long)(kt + 1) * BK * ldB);
        }
#pragma unroll
        for (int kk = 0; kk < BK; ++kk) {
            float4 av  = *(const float4*)&As[cur][kk][ty * 4];
            float4 bgv = *(const float4*)&Bgs[cur][kk][tx * 4];
            float4 buv = *(const float4*)&Bus[cur][kk][tx * 4];
            unsigned long long a0 = pk2(av.x, av.x), a1 = pk2(av.y, av.y);
            unsigned long long a2 = pk2(av.z, av.z), a3 = pk2(av.w, av.w);
            unsigned long long b0 = pk2(bgv.x, bgv.y), b1 = pk2(bgv.z, bgv.w);
            unsigned long long c0 = pk2(buv.x, buv.y), c1 = pk2(buv.z, buv.w);
            ffma2(accg[0][0], a0, b0); ffma2(accg[0][1], a0, b1);
            ffma2(accg[1][0], a1, b0); ffma2(accg[1][1], a1, b1);
            ffma2(accg[2][0], a2, b0); ffma2(accg[2][1], a2, b1);
            ffma2(accg[3][0], a3, b0); ffma2(accg[3][1], a3, b1);
            ffma2(accu[0][0], a0, c0); ffma2(accu[0][1], a0, c1);
            ffma2(accu[1][0], a1, c0); ffma2(accu[1][1], a1, c1);
            ffma2(accu[2][0], a2, c0); ffma2(accu[2][1], a2, c1);
            ffma2(accu[3][0], a3, c0); ffma2(accu[3][1], a3, c1);
        }
        if (more) {
            const int nx = cur ^ 1;
            As[nx][lc * 4 + 0][lr] = ra.x;
            As[nx][lc * 4 + 1][lr] = ra.y;
            As[nx][lc * 4 + 2][lr] = ra.z;
            As[nx][lc * 4 + 3][lr] = ra.w;
            *(float4*)&Bgs[nx][lbk][lbn * 4] = rbg;
            *(float4*)&Bus[nx][lbk][lbn * 4] = rbu;
        }
        __syncthreads();
    }

    // epilogue
#pragma unroll
    for (int i = 0; i < 4; ++i) {
        const int r = row0 + ty * 4 + i;
        if (r < M) {
            float* crow = Ce + (long long)r * ldC + col0 + tx * 4;
#pragma unroll
            for (int j = 0; j < 2; ++j) {
                float2 gv = upk2(accg[i][j]);
                float2 uv = upk2(accu[i][j]);
                if (SILU) {
                    float2 o;
                    o.x = gv.x / (1.f + expf(-gv.x)) * uv.x;
                    o.y = gv.y / (1.f + expf(-gv.y)) * uv.y;
                    *(float2*)(crow + j * 2) = o;
                } else {
                    *(float2*)(crow + j * 2)            = gv;
                    *(float2*)(crow + pair_off + j * 2) = uv;
                }
            }
        }
    }
}

// ---------------- combine: out = shared + SCALE * sum_k w_k * y[slot_k] ----------------
__global__ void combine_kernel(float* __restrict__ out) {
    const int t = blockIdx.x;
    const int c = threadIdx.x;  // float4 index 0..255
    float4 sh = *(const float4*)(g_shared + (long long)t * HDIM + c * 4);
    float ax = 0.f, ay = 0.f, az = 0.f, aw = 0.f;
#pragma unroll
    for (int k = 0; k < TOPK; ++k) {
        const int slot = g_slot_of_a[t * TOPK + k];
        const float w = g_topk_w[t * TOPK + k];
        if (slot >= 0) {
            float4 v = *(const float4*)(g_y + (long long)slot * HDIM + c * 4);
            ax += w * v.x; ay += w * v.y; az += w * v.z; aw += w * v.w;
        }
    }
    float4 o;
    o.x = sh.x + SCALE_F * ax;
    o.y = sh.y + SCALE_F * ay;
    o.z = sh.z + SCALE_F * az;
    o.w = sh.w + SCALE_F * aw;
    *(float4*)(out + (long long)t * HDIM + c * 4) = o;
}

// ---------------- host launch ----------------
extern "C" void kernel_launch(void* const* d_in, const int* in_sizes, int n_in,
                              void* d_out, int out_size) {
    (void)in_sizes; (void)n_in; (void)out_size;
    const float* x          = (const float*)d_in[0];   // [T,H]
    const float* gate_w     = (const float*)d_in[1];   // [H,E]
    const float* e_bias     = (const float*)d_in[2];   // [E]
    const float* w_gate_up  = (const float*)d_in[3];   // [E,H,2I]
    const float* w_down     = (const float*)d_in[4];   // [E,I,H]
    const float* ws_gate_up = (const float*)d_in[5];   // [H,2048]
    const float* ws_down    = (const float*)d_in[6];   // [1024,H]
    float* out = (float*)d_out;

    float *p_act, *p_y, *p_shact, *p_shared;
    cudaGetSymbolAddress((void**)&p_act,    g_act);
    cudaGetSymbolAddress((void**)&p_y,      g_y);
    cudaGetSymbolAddress((void**)&p_shact,  g_shact);
    cudaGetSymbolAddress((void**)&p_shared, g_shared);

    zero_cnt_kernel<<<1, 64>>>();
    router_kernel<<<T_TOK, 256>>>(x, gate_w, e_bias);

    // routed gate_up + silu*mul : act[e,slot,0:I]
    sgemm_moe<MODE_GATHER, true><<<dim3(IDIM / BN, CAP / BM, NEXP), 256>>>(
        x, w_gate_up, p_act,
        /*K*/ HDIM, /*ldA*/ HDIM, /*ldB*/ 2 * IDIM, /*ldC*/ IDIM,
        /*pair_off*/ IDIM,
        /*strideAe*/ 0LL, /*strideBe*/ (long long)HDIM * 2 * IDIM,
        /*strideCe*/ (long long)CAP * IDIM, /*Mfixed*/ 0);

    // routed down : y[e,slot,0:H]
    sgemm_moe<MODE_EXPOFF, false><<<dim3(HDIM / (2 * BN), CAP / BM, NEXP), 256>>>(
        p_act, w_down, p_y,
        /*K*/ IDIM, /*ldA*/ IDIM, /*ldB*/ HDIM, /*ldC*/ HDIM,
        /*pair_off*/ BN,
        /*strideAe*/ (long long)CAP * IDIM, /*strideBe*/ (long long)IDIM * HDIM,
        /*strideCe*/ (long long)CAP * HDIM, /*Mfixed*/ 0);

    // shared gate_up + silu*mul : shact[T,1024]
    sgemm_moe<MODE_DIRECT, true><<<dim3(1024 / BN, T_TOK / BM, 1), 256>>>(
        x, ws_gate_up, p_shact,
        /*K*/ HDIM, /*ldA*/ HDIM, /*ldB*/ 2048, /*ldC*/ 1024,
        /*pair_off*/ 1024,
        0LL, 0LL, 0LL, /*Mfixed*/ T_TOK);

    // shared down : g_shared[T,H]
    sgemm_moe<MODE_DIRECT, false><<<dim3(HDIM / (2 * BN), T_TOK / BM, 1), 256>>>(
        p_shact, ws_down, p_shared,
        /*K*/ 1024, /*ldA*/ 1024, /*ldB*/ HDIM, /*ldC*/ HDIM,
        /*pair_off*/ BN,
        0LL, 0LL, 0LL, /*Mfixed*/ T_TOK);

    combine_kernel<<<T_TOK, 256>>>(out);
}